// round 6
// baseline (speedup 1.0000x reference)
#include <cuda_runtime.h>
#include <cuda_bf16.h>
#include <math.h>

// Problem constants
#define BB    2
#define LQ_   2048
#define LK_   2048
#define EE    1024
#define HH    16
#define DKK   64
#define DVV   64
#define TOPK_ 64
#define QT    8      // q rows per fused CTA

// Device scratch
__device__ __align__(256) float g_qp [BB*HH*LQ_*DKK];   // [bh][q][d]
__device__ __align__(256) float g_kp [BB*HH*LK_*DKK];   // [bh][k][d]
__device__ __align__(256) float g_kpt[BB*HH*DKK*LK_];   // [bh][d][k]
__device__ __align__(256) float g_vp [BB*HH*LK_*DVV];   // [bh][k][d]
__device__ __align__(256) float g_mix[BB*LQ_*HH*DVV];   // [b,q][h*64+d]

// --------------------------- f32x2 helpers --------------------------------
typedef unsigned long long ull;
__device__ __forceinline__ ull dup2(float x) {
    ull r; asm("mov.b64 %0, {%1, %1};" : "=l"(r) : "f"(x)); return r;
}
__device__ __forceinline__ ull fma2(ull a, ull b, ull c) {
    ull d; asm("fma.rn.f32x2 %0, %1, %2, %3;" : "=l"(d) : "l"(a), "l"(b), "l"(c)); return d;
}
__device__ __forceinline__ float2 unp2(ull p) {
    float2 f; asm("mov.b64 {%0, %1}, %2;" : "=f"(f.x), "=f"(f.y) : "l"(p)); return f;
}

// ---------------------------------------------------------------------------
// 128x128 tile, 8x8 micro-tile SGEMM, f32x2 FMA, double-buffered (R4, passing).
// C = A * W^T. mode 0: scatter to [(b*nH+h)*Lrows+l]*64+d; mode 1: row-major.
// ---------------------------------------------------------------------------
__global__ void __launch_bounds__(256, 2) sgemm128(
    const float* __restrict__ A, const float* __restrict__ W, float* __restrict__ C,
    int M, int N, int K, int mode, float scale, int Lrows,
    size_t sA, size_t sW, size_t sC)
{
    A += (size_t)blockIdx.z * sA;
    W += (size_t)blockIdx.z * sW;
    C += (size_t)blockIdx.z * sC;
    const int m0 = blockIdx.y * 128;
    const int n0 = blockIdx.x * 128;
    const int tid = threadIdx.x;
    const int ty = tid >> 4;
    const int tx = tid & 15;
    const int lr = tid >> 1;
    const int lc = (tid & 1) << 2;

    __shared__ __align__(16) float As[2][8][132];
    __shared__ __align__(16) float Ws[2][8][132];

    ull accp[8][4];
    #pragma unroll
    for (int i = 0; i < 8; i++)
        #pragma unroll
        for (int j = 0; j < 4; j++) accp[i][j] = 0ull;

    const float* Arow = A + (size_t)(m0 + lr) * K + lc;
    const float* Wrow = W + (size_t)(n0 + lr) * K + lc;
    {
        float4 a = *(const float4*)(Arow);
        float4 w = *(const float4*)(Wrow);
        As[0][lc+0][lr] = a.x; As[0][lc+1][lr] = a.y; As[0][lc+2][lr] = a.z; As[0][lc+3][lr] = a.w;
        Ws[0][lc+0][lr] = w.x; Ws[0][lc+1][lr] = w.y; Ws[0][lc+2][lr] = w.z; Ws[0][lc+3][lr] = w.w;
    }
    __syncthreads();

    const int nT = K >> 3;
    for (int t = 0; t < nT; t++) {
        const int cur = t & 1;
        float4 an, wn;
        const bool more = (t + 1 < nT);
        if (more) {
            an = *(const float4*)(Arow + (t + 1) * 8);
            wn = *(const float4*)(Wrow + (t + 1) * 8);
        }
        #pragma unroll
        for (int e = 0; e < 8; e++) {
            float4 a0 = *(const float4*)&As[cur][e][ty * 8];
            float4 a1 = *(const float4*)&As[cur][e][ty * 8 + 4];
            ulonglong2 bp0 = *(const ulonglong2*)&Ws[cur][e][tx * 8];
            ulonglong2 bp1 = *(const ulonglong2*)&Ws[cur][e][tx * 8 + 4];
            ull bv[4] = {bp0.x, bp0.y, bp1.x, bp1.y};
            float av[8] = {a0.x, a0.y, a0.z, a0.w, a1.x, a1.y, a1.z, a1.w};
            #pragma unroll
            for (int i = 0; i < 8; i++) {
                ull ad = dup2(av[i]);
                #pragma unroll
                for (int j = 0; j < 4; j++)
                    accp[i][j] = fma2(ad, bv[j], accp[i][j]);
            }
        }
        if (more) {
            const int nxt = cur ^ 1;
            As[nxt][lc+0][lr] = an.x; As[nxt][lc+1][lr] = an.y;
            As[nxt][lc+2][lr] = an.z; As[nxt][lc+3][lr] = an.w;
            Ws[nxt][lc+0][lr] = wn.x; Ws[nxt][lc+1][lr] = wn.y;
            Ws[nxt][lc+2][lr] = wn.z; Ws[nxt][lc+3][lr] = wn.w;
            __syncthreads();
        }
    }

    const int nH = N >> 6;
    #pragma unroll
    for (int i = 0; i < 8; i++) {
        int m = m0 + ty * 8 + i;
        #pragma unroll
        for (int j2 = 0; j2 < 2; j2++) {
            float2 p0 = unp2(accp[i][j2*2+0]);
            float2 p1 = unp2(accp[i][j2*2+1]);
            float4 o = make_float4(p0.x*scale, p0.y*scale, p1.x*scale, p1.y*scale);
            int n = n0 + tx * 8 + j2 * 4;
            if (mode == 0) {
                int b = m / Lrows, l = m - b * Lrows;
                int h = n >> 6, d = n & 63;
                *(float4*)&C[(((size_t)b * nH + h) * Lrows + l) * 64 + d] = o;
            } else {
                *(float4*)&C[(size_t)m * N + n] = o;
            }
        }
    }
}

// ---------------------------------------------------------------------------
// Small GEMM kept for fc (N=64): C = A*W^T, 64x64 tile, 4x4 micro.
// ---------------------------------------------------------------------------
__global__ __launch_bounds__(256) void sgemm_nt(
    const float* __restrict__ A, const float* __restrict__ W, float* __restrict__ C,
    int M, int N, int K, float scale)
{
    const int m0 = blockIdx.y * 64;
    const int n0 = blockIdx.x * 64;
    const int tid = threadIdx.x;
    const int ty = tid >> 4;
    const int tx = tid & 15;

    __shared__ __align__(16) float As[32][68];
    __shared__ __align__(16) float Ws[32][68];

    float acc[4][4];
    #pragma unroll
    for (int i = 0; i < 4; i++)
        #pragma unroll
        for (int j = 0; j < 4; j++) acc[i][j] = 0.f;

    for (int kt = 0; kt < K; kt += 32) {
        #pragma unroll
        for (int i = 0; i < 2; i++) {
            int f  = tid + i * 256;
            int r  = f >> 3;
            int c4 = (f & 7) << 2;
            float4 a = *(const float4*)(A + (size_t)(m0 + r) * K + kt + c4);
            As[c4+0][r] = a.x; As[c4+1][r] = a.y; As[c4+2][r] = a.z; As[c4+3][r] = a.w;
            float4 w = *(const float4*)(W + (size_t)(n0 + r) * K + kt + c4);
            Ws[c4+0][r] = w.x; Ws[c4+1][r] = w.y; Ws[c4+2][r] = w.z; Ws[c4+3][r] = w.w;
        }
        __syncthreads();
        #pragma unroll
        for (int e = 0; e < 32; e++) {
            float4 ra = *(const float4*)&As[e][ty << 2];
            float4 rb = *(const float4*)&Ws[e][tx << 2];
            float av[4] = {ra.x, ra.y, ra.z, ra.w};
            float bv[4] = {rb.x, rb.y, rb.z, rb.w};
            #pragma unroll
            for (int i = 0; i < 4; i++)
                #pragma unroll
                for (int j = 0; j < 4; j++)
                    acc[i][j] += av[i] * bv[j];
        }
        __syncthreads();
    }
    #pragma unroll
    for (int i = 0; i < 4; i++) {
        int m = m0 + (ty << 2) + i;
        #pragma unroll
        for (int j = 0; j < 4; j++) {
            int n = n0 + (tx << 2) + j;
            C[(size_t)m * N + n] = acc[i][j] * scale;
        }
    }
}

// ---------------------------------------------------------------------------
// KP transpose: [bh][k][64] -> [bh][d][2048], 64x64 tiles, coalesced both ways
// ---------------------------------------------------------------------------
__global__ __launch_bounds__(256) void transpose_kp(
    const float* __restrict__ in, float* __restrict__ out)
{
    __shared__ float t[64][65];
    const int plane = blockIdx.y;
    const int k0 = blockIdx.x * 64;
    const float* ip = in + (size_t)plane * LK_ * 64;
    float* op = out + (size_t)plane * 64 * LK_;
    #pragma unroll
    for (int s = 0; s < 4; s++) {
        int idx = threadIdx.x + s * 256;
        int kr = idx >> 4;
        int d4 = (idx & 15) << 2;
        float4 v = *(const float4*)(ip + (size_t)(k0 + kr) * 64 + d4);
        t[d4+0][kr] = v.x; t[d4+1][kr] = v.y; t[d4+2][kr] = v.z; t[d4+3][kr] = v.w;
    }
    __syncthreads();
    #pragma unroll
    for (int s = 0; s < 4; s++) {
        int idx = threadIdx.x + s * 256;
        int dr = idx >> 4;
        int k4 = (idx & 15) << 2;
        float4 v = make_float4(t[dr][k4], t[dr][k4+1], t[dr][k4+2], t[dr][k4+3]);
        *(float4*)(op + (size_t)dr * LK_ + k0 + k4) = v;
    }
}

// ---------------------------------------------------------------------------
// Fused: logits GEMM (8q x 2048k, regs) + radix top-64 + softmax + AV + attn
// ---------------------------------------------------------------------------
__device__ __forceinline__ unsigned encf(float x) {
    unsigned u = __float_as_uint(x);
    return (u & 0x80000000u) ? ~u : (u | 0x80000000u);
}
__device__ __forceinline__ float decf(unsigned u) {
    return (u & 0x80000000u) ? __uint_as_float(u ^ 0x80000000u) : __uint_as_float(~u);
}
__device__ __forceinline__ int warp_incl_scan(int v, int lane) {
    #pragma unroll
    for (int o = 1; o < 32; o <<= 1) {
        int n = __shfl_up_sync(0xffffffffu, v, o);
        if (lane >= o) v += n;
    }
    return v;
}
__device__ __forceinline__ int ballot_append(bool flag, int* counter, int lane) {
    unsigned m = __ballot_sync(0xffffffffu, flag);
    int base = 0;
    if (m) {
        int leader = __ffs(m) - 1;
        if (lane == leader) base = atomicAdd(counter, __popc(m));
        base = __shfl_sync(0xffffffffu, base, leader);
    }
    return base + __popc(m & ((1u << lane) - 1u));
}
// 512-thread digit pick: threads 0..255 own one bin each
__device__ __forceinline__ void pick_digit512(
    const int* hist, int kk, int tid, int lane, int wid,
    int* wtot, int* s_d, int* s_k)
{
    int ps = (tid < 256) ? hist[tid] : 0;
    int incl = warp_incl_scan(ps, lane);
    if (lane == 31) wtot[wid] = incl;
    __syncthreads();
    int base = 0, Tot = 0;
    #pragma unroll
    for (int w2 = 0; w2 < 16; w2++) { int v = wtot[w2]; if (w2 < wid) base += v; Tot += v; }
    int inclAll = incl + base;
    int S_t  = Tot - inclAll + ps;   // suffix sum from bin tid
    int S_t1 = S_t - ps;             // suffix sum from bin tid+1
    if (tid < 256 && S_t >= kk && S_t1 < kk) { *s_d = tid; *s_k = kk - S_t1; }
    __syncthreads();
}

// dynamic smem layout (bytes)
#define OFF_LG    0                         // QT*2048 floats = 65536 B
#define OFF_QPD   65536                     // 8*64 ull = 4096 B
#define OFF_CAND  69632                     // 2048 int = 8192 B
#define OFF_HIST  77824                     // 256 int = 1024
#define OFF_WTOT  78848                     // 16 int
#define OFF_WMAX  78912                     // 16 u32
#define OFF_SRED  78976                     // 512 float = 2048
#define OFF_SELI  81024                     // 64 int
#define OFF_SELW  81280                     // 64 float
#define OFF_WSUM  81536                     // 16 float
#define OFF_SCAL  81600                     // scalars
#define SMEM_FUSED 81664

__global__ void __launch_bounds__(512, 2) fused_attn(
    const float* __restrict__ qp, const float* __restrict__ kpt,
    const float* __restrict__ vp, float* __restrict__ mix,
    float* __restrict__ attn, int write_attn)
{
    extern __shared__ __align__(16) char dsm[];
    float*    LG   = (float*)(dsm + OFF_LG);
    ull*      QPD  = (ull*)(dsm + OFF_QPD);
    int*      cand = (int*)(dsm + OFF_CAND);
    int*      hist = (int*)(dsm + OFF_HIST);
    int*      wtot = (int*)(dsm + OFF_WTOT);
    unsigned* wmax = (unsigned*)(dsm + OFF_WMAX);
    float*    sred = (float*)(dsm + OFF_SRED);
    int*      sel_idx = (int*)(dsm + OFF_SELI);
    float*    sel_w   = (float*)(dsm + OFF_SELW);
    float*    wsum    = (float*)(dsm + OFF_WSUM);
    int*      s_int = (int*)(dsm + OFF_SCAL);      // [0]=s_d [1]=s_k [2]=nsel [3]=ncand
    float*    s_flt = (float*)(dsm + OFF_SCAL + 16); // [0]=max [1]=invZ

    const int tid  = threadIdx.x;
    const int lane = tid & 31;
    const int wid  = tid >> 5;
    const int bh   = blockIdx.y;
    const int q0   = blockIdx.x * QT;
    const int b    = bh >> 4;
    const int h    = bh & 15;

    // --- QP tile (dup2-packed) ---
    {
        int qq = tid >> 6, d = tid & 63;
        float qv = qp[((size_t)bh * LQ_ + q0 + qq) * 64 + d];
        QPD[qq * 64 + d] = dup2(qv);
    }
    __syncthreads();

    // --- logits GEMM: thread owns 4 k-cols, 8 q rows in registers ---
    {
        const int ct = tid << 2;
        const float* src = kpt + (size_t)bh * 64 * LK_ + ct;
        ull acc[QT][2];
        #pragma unroll
        for (int qq = 0; qq < QT; qq++) { acc[qq][0] = 0ull; acc[qq][1] = 0ull; }
        #pragma unroll 4
        for (int d = 0; d < 64; d++) {
            ulonglong2 kv = *(const ulonglong2*)(src + (size_t)d * LK_);
            #pragma unroll
            for (int qq = 0; qq < QT; qq++) {
                ull qd = QPD[qq * 64 + d];
                acc[qq][0] = fma2(qd, kv.x, acc[qq][0]);
                acc[qq][1] = fma2(qd, kv.y, acc[qq][1]);
            }
        }
        #pragma unroll
        for (int qq = 0; qq < QT; qq++) {
            float2 p0 = unp2(acc[qq][0]);
            float2 p1 = unp2(acc[qq][1]);
            *(float4*)&LG[qq * LK_ + ct] = make_float4(p0.x, p0.y, p1.x, p1.y);
        }
    }
    __syncthreads();

    // --- per-row selection ---
    for (int r = 0; r < QT; r++) {
        float* lrow = LG + r * LK_;
        unsigned* su = (unsigned*)lrow;

        if (tid < 256) hist[tid] = 0;
        if (tid == 0) { s_int[2] = 0; s_int[3] = 0; }
        __syncthreads();

        // encode in place + max + top-byte hist (thread owns elems tid*4..+3)
        float4 x = ((float4*)lrow)[tid];
        unsigned e0 = encf(x.x), e1 = encf(x.y), e2 = encf(x.z), e3 = encf(x.w);
        ((uint4*)su)[tid] = make_uint4(e0, e1, e2, e3);
        unsigned lm = e0 > e1 ? e0 : e1;
        unsigned m23 = e2 > e3 ? e2 : e3;
        lm = lm > m23 ? lm : m23;
        #pragma unroll
        for (int o = 16; o > 0; o >>= 1) {
            unsigned v = __shfl_xor_sync(0xffffffffu, lm, o);
            lm = lm > v ? lm : v;
        }
        if (lane == 0) wmax[wid] = lm;
        unsigned ee[4] = {e0, e1, e2, e3};
        #pragma unroll
        for (int j = 0; j < 4; j++) {
            int dg = (int)(ee[j] >> 24);
            unsigned mm = __match_any_sync(0xffffffffu, dg);
            if ((int)(__ffs(mm) - 1) == lane) atomicAdd(&hist[dg], __popc(mm));
        }
        __syncthreads();
        if (tid == 0) {
            unsigned m = wmax[0];
            #pragma unroll
            for (int w2 = 1; w2 < 16; w2++) m = m > wmax[w2] ? m : wmax[w2];
            s_flt[0] = decf(m);
        }
        pick_digit512(hist, TOPK_, tid, lane, wid, wtot, &s_int[0], &s_int[1]);
        const float rowmax = s_flt[0];
        int d1 = s_int[0];
        int kk = s_int[1];

        // compact boundary bin (indices tid*4+j, keys in regs)
        #pragma unroll
        for (int j = 0; j < 4; j++) {
            int dg = (int)(ee[j] >> 24);
            bool is_g = dg > d1;
            bool is_e = dg == d1;
            int pg = ballot_append(is_g, &s_int[2], lane);
            if (is_g) sel_idx[pg] = tid * 4 + j;
            int pe = ballot_append(is_e, &s_int[3], lane);
            if (is_e) cand[pe] = tid * 4 + j;
        }
        __syncthreads();
        int C = s_int[3];

        for (int shift = 16; shift >= 0; shift -= 8) {
            if (C == kk) break;
            if (tid < 256) hist[tid] = 0;
            __syncthreads();
            for (int c = tid; c < C; c += 512)
                atomicAdd(&hist[(su[cand[c]] >> shift) & 255u], 1);
            __syncthreads();
            pick_digit512(hist, kk, tid, lane, wid, wtot, &s_int[0], &s_int[1]);
            int d = s_int[0];
            int mine[4]; int nm = 0;
            for (int c = tid; c < C; c += 512) mine[nm++] = cand[c];
            __syncthreads();
            if (tid == 0) s_int[3] = 0;
            __syncthreads();
            int Cpad = (C + 511) & ~511;
            int used = 0;
            for (int c0 = 0; c0 < Cpad; c0 += 512) {
                int c = c0 + tid;
                bool active = (c < C);
                int idx = active ? mine[used] : 0;
                if (active) used++;
                int dg = active ? (int)((su[idx] >> shift) & 255u) : -1;
                bool is_g = active && (dg > d);
                bool is_e = active && (dg == d);
                int pg = ballot_append(is_g, &s_int[2], lane);
                if (is_g) sel_idx[pg] = idx;
                int pe = ballot_append(is_e, &s_int[3], lane);
                if (is_e) cand[pe] = idx;
            }
            __syncthreads();
            C = s_int[3];
            kk = s_int[1];
        }

        if (C == kk) {
            for (int c = tid; c < C; c += 512) {
                int pos = atomicAdd(&s_int[2], 1);
                sel_idx[pos] = cand[c];
            }
        } else {
            // full-key ties: keep kk lowest indices (jax semantics)
            for (int c = tid; c < C; c += 512) {
                int idx = cand[c];
                int rk = 0;
                for (int j = 0; j < C; j++) rk += (cand[j] < idx);
                if (rk < kk) { int pos = atomicAdd(&s_int[2], 1); sel_idx[pos] = idx; }
            }
        }
        __syncthreads();

        // softmax over 64 selected
        float w = 0.f;
        if (tid < TOPK_) {
            w = expf(decf(su[sel_idx[tid]]) - rowmax);
            sel_w[tid] = w;
        }
        float zl = w;
        #pragma unroll
        for (int o = 16; o > 0; o >>= 1) zl += __shfl_xor_sync(0xffffffffu, zl, o);
        if (tid < TOPK_ && lane == 0) wsum[wid] = zl;
        __syncthreads();
        if (tid == 0) s_flt[1] = 1.0f / (wsum[0] + wsum[1]);
        __syncthreads();
        const float invZ = s_flt[1];
        if (tid < TOPK_) sel_w[tid] = sel_w[tid] * invZ;
        __syncthreads();

        // attn row: zero smem row, scatter 64, stream out coalesced
        if (write_attn) {
            ((float4*)lrow)[tid] = make_float4(0.f, 0.f, 0.f, 0.f);
            __syncthreads();
            if (tid < TOPK_) lrow[sel_idx[tid]] = sel_w[tid];
            __syncthreads();
            float4* arow4 = (float4*)(attn + ((size_t)bh * LQ_ + q0 + r) * LK_);
            arow4[tid] = ((float4*)lrow)[tid];
        }

        // sparse AV
        {
            const int dd = tid & 63, sl = tid >> 6;    // 8 slices
            const float* vb = vp + (size_t)bh * LK_ * 64;
            float accv = 0.f;
            #pragma unroll
            for (int s = 0; s < 8; s++) {
                int si = sl * 8 + s;
                accv += sel_w[si] * vb[(size_t)sel_idx[si] * 64 + dd];
            }
            sred[tid] = accv;
            __syncthreads();
            if (tid < 64) {
                float t = 0.f;
                #pragma unroll
                for (int s = 0; s < 8; s++) t += sred[s * 64 + tid];
                mix[((size_t)(b * LQ_ + q0 + r)) * (HH * DVV) + h * 64 + tid] = t;
            }
            __syncthreads();
        }
    }
}

// ---------------------------------------------------------------------------
extern "C" void kernel_launch(void* const* d_in, const int* in_sizes, int n_in,
                              void* d_out, int out_size) {
    (void)in_sizes; (void)n_in;
    const float* q    = (const float*)d_in[0];
    const float* k    = (const float*)d_in[1];
    const float* v    = (const float*)d_in[2];
    const float* w_qs = (const float*)d_in[3];
    const float* w_ks = (const float*)d_in[4];
    const float* w_vs = (const float*)d_in[5];
    const float* fc   = (const float*)d_in[6];
    float* out = (float*)d_out;

    float *qp, *kp, *kpt, *vp, *mix;
    cudaGetSymbolAddress((void**)&qp,  g_qp);
    cudaGetSymbolAddress((void**)&kp,  g_kp);
    cudaGetSymbolAddress((void**)&kpt, g_kpt);
    cudaGetSymbolAddress((void**)&vp,  g_vp);
    cudaGetSymbolAddress((void**)&mix, g_mix);

    const long long out_elems  = (long long)BB * LQ_ * DVV;           // 262144
    const long long attn_elems = (long long)BB * HH * LQ_ * LK_;      // 134217728
    int write_attn = ((long long)out_size >= out_elems + attn_elems) ? 1 : 0;
    float* attn = out + out_elems;

    cudaFuncSetAttribute(fused_attn, cudaFuncAttributeMaxDynamicSharedMemorySize, SMEM_FUSED);

    dim3 blk(256);
    // QP = (q @ w_qs^T) * 0.125
    sgemm128<<<dim3(8, 32, 1), blk>>>(q, w_qs, qp, BB*LQ_, HH*DKK, EE, 0, 0.125f, LQ_, 0, 0, 0);
    // KP = k @ w_ks^T
    sgemm128<<<dim3(8, 32, 1), blk>>>(k, w_ks, kp, BB*LK_, HH*DKK, EE, 0, 1.0f, LK_, 0, 0, 0);
    // KPT = transpose(KP) per plane
    transpose_kp<<<dim3(32, 32), blk>>>(kp, kpt);
    // VP = v @ w_vs^T
    sgemm128<<<dim3(8, 32, 1), blk>>>(v, w_vs, vp, BB*LK_, HH*DVV, DVV, 0, 1.0f, LK_, 0, 0, 0);

    // fused logits + top-k + softmax + AV + attn write
    fused_attn<<<dim3(LQ_ / QT, BB * HH), 512, SMEM_FUSED>>>(qp, kpt, vp, mix, attn, write_attn);

    // out = mix @ fc^T
    sgemm_nt<<<dim3(1, 64, 1), blk>>>(mix, fc, out, BB*LQ_, DVV, HH*DVV, 1.0f);
}

// round 8
// speedup vs baseline: 1.4193x; 1.4193x over previous
#include <cuda_runtime.h>
#include <cuda_bf16.h>
#include <math.h>

// Problem constants
#define BB    2
#define LQ_   2048
#define LK_   2048
#define EE    1024
#define HH    16
#define DKK   64
#define DVV   64
#define TOPK_ 64

// Device scratch
__device__ __align__(256) float g_qp[BB*HH*LQ_*DKK];
__device__ __align__(256) float g_kp[BB*HH*LK_*DKK];
__device__ __align__(256) float g_vp[BB*HH*LK_*DVV];
__device__ __align__(256) float g_mix[BB*LQ_*HH*DVV];
__device__ __align__(256) float g_logits[(size_t)BB*HH*LQ_*LK_]; // 512MB

// --------------------------- f32x2 helpers --------------------------------
typedef unsigned long long ull;
__device__ __forceinline__ ull dup2(float x) {
    ull r; asm("mov.b64 %0, {%1, %1};" : "=l"(r) : "f"(x)); return r;
}
__device__ __forceinline__ ull fma2(ull a, ull b, ull c) {
    ull d; asm("fma.rn.f32x2 %0, %1, %2, %3;" : "=l"(d) : "l"(a), "l"(b), "l"(c)); return d;
}
__device__ __forceinline__ float2 unp2(ull p) {
    float2 f; asm("mov.b64 {%0, %1}, %2;" : "=f"(f.x), "=f"(f.y) : "l"(p)); return f;
}

// ---------------------------------------------------------------------------
// 128x128 tile, 8x8 micro-tile SGEMM, f32x2 FMA, double-buffered (R4, passing).
// ---------------------------------------------------------------------------
__global__ void __launch_bounds__(256, 2) sgemm128(
    const float* __restrict__ A, const float* __restrict__ W, float* __restrict__ C,
    int M, int N, int K, int mode, float scale, int Lrows,
    size_t sA, size_t sW, size_t sC)
{
    A += (size_t)blockIdx.z * sA;
    W += (size_t)blockIdx.z * sW;
    C += (size_t)blockIdx.z * sC;
    const int m0 = blockIdx.y * 128;
    const int n0 = blockIdx.x * 128;
    const int tid = threadIdx.x;
    const int ty = tid >> 4;
    const int tx = tid & 15;
    const int lr = tid >> 1;
    const int lc = (tid & 1) << 2;

    __shared__ __align__(16) float As[2][8][132];
    __shared__ __align__(16) float Ws[2][8][132];

    ull accp[8][4];
    #pragma unroll
    for (int i = 0; i < 8; i++)
        #pragma unroll
        for (int j = 0; j < 4; j++) accp[i][j] = 0ull;

    const float* Arow = A + (size_t)(m0 + lr) * K + lc;
    const float* Wrow = W + (size_t)(n0 + lr) * K + lc;
    {
        float4 a = *(const float4*)(Arow);
        float4 w = *(const float4*)(Wrow);
        As[0][lc+0][lr] = a.x; As[0][lc+1][lr] = a.y; As[0][lc+2][lr] = a.z; As[0][lc+3][lr] = a.w;
        Ws[0][lc+0][lr] = w.x; Ws[0][lc+1][lr] = w.y; Ws[0][lc+2][lr] = w.z; Ws[0][lc+3][lr] = w.w;
    }
    __syncthreads();

    const int nT = K >> 3;
    for (int t = 0; t < nT; t++) {
        const int cur = t & 1;
        float4 an, wn;
        const bool more = (t + 1 < nT);
        if (more) {
            an = *(const float4*)(Arow + (t + 1) * 8);
            wn = *(const float4*)(Wrow + (t + 1) * 8);
        }
        #pragma unroll
        for (int e = 0; e < 8; e++) {
            float4 a0 = *(const float4*)&As[cur][e][ty * 8];
            float4 a1 = *(const float4*)&As[cur][e][ty * 8 + 4];
            ulonglong2 bp0 = *(const ulonglong2*)&Ws[cur][e][tx * 8];
            ulonglong2 bp1 = *(const ulonglong2*)&Ws[cur][e][tx * 8 + 4];
            ull bv[4] = {bp0.x, bp0.y, bp1.x, bp1.y};
            float av[8] = {a0.x, a0.y, a0.z, a0.w, a1.x, a1.y, a1.z, a1.w};
            #pragma unroll
            for (int i = 0; i < 8; i++) {
                ull ad = dup2(av[i]);
                #pragma unroll
                for (int j = 0; j < 4; j++)
                    accp[i][j] = fma2(ad, bv[j], accp[i][j]);
            }
        }
        if (more) {
            const int nxt = cur ^ 1;
            As[nxt][lc+0][lr] = an.x; As[nxt][lc+1][lr] = an.y;
            As[nxt][lc+2][lr] = an.z; As[nxt][lc+3][lr] = an.w;
            Ws[nxt][lc+0][lr] = wn.x; Ws[nxt][lc+1][lr] = wn.y;
            Ws[nxt][lc+2][lr] = wn.z; Ws[nxt][lc+3][lr] = wn.w;
            __syncthreads();
        }
    }

    const int nH = N >> 6;
    #pragma unroll
    for (int i = 0; i < 8; i++) {
        int m = m0 + ty * 8 + i;
        #pragma unroll
        for (int j2 = 0; j2 < 2; j2++) {
            float2 p0 = unp2(accp[i][j2*2+0]);
            float2 p1 = unp2(accp[i][j2*2+1]);
            float4 o = make_float4(p0.x*scale, p0.y*scale, p1.x*scale, p1.y*scale);
            int n = n0 + tx * 8 + j2 * 4;
            if (mode == 0) {
                int b = m / Lrows, l = m - b * Lrows;
                int h = n >> 6, d = n & 63;
                *(float4*)&C[(((size_t)b * nH + h) * Lrows + l) * 64 + d] = o;
            } else {
                *(float4*)&C[(size_t)m * N + n] = o;
            }
        }
    }
}

// ---------------------------------------------------------------------------
// Small GEMM kept for fc (N=64): C = A*W^T, 64x64 tile, 4x4 micro.
// ---------------------------------------------------------------------------
__global__ __launch_bounds__(256) void sgemm_nt(
    const float* __restrict__ A, const float* __restrict__ W, float* __restrict__ C,
    int M, int N, int K, float scale)
{
    const int m0 = blockIdx.y * 64;
    const int n0 = blockIdx.x * 64;
    const int tid = threadIdx.x;
    const int ty = tid >> 4;
    const int tx = tid & 15;

    __shared__ __align__(16) float As[32][68];
    __shared__ __align__(16) float Ws[32][68];

    float acc[4][4];
    #pragma unroll
    for (int i = 0; i < 4; i++)
        #pragma unroll
        for (int j = 0; j < 4; j++) acc[i][j] = 0.f;

    for (int kt = 0; kt < K; kt += 32) {
        #pragma unroll
        for (int i = 0; i < 2; i++) {
            int f  = tid + i * 256;
            int r  = f >> 3;
            int c4 = (f & 7) << 2;
            float4 a = *(const float4*)(A + (size_t)(m0 + r) * K + kt + c4);
            As[c4+0][r] = a.x; As[c4+1][r] = a.y; As[c4+2][r] = a.z; As[c4+3][r] = a.w;
            float4 w = *(const float4*)(W + (size_t)(n0 + r) * K + kt + c4);
            Ws[c4+0][r] = w.x; Ws[c4+1][r] = w.y; Ws[c4+2][r] = w.z; Ws[c4+3][r] = w.w;
        }
        __syncthreads();
        #pragma unroll
        for (int e = 0; e < 32; e++) {
            float4 ra = *(const float4*)&As[e][ty << 2];
            float4 rb = *(const float4*)&Ws[e][tx << 2];
            float av[4] = {ra.x, ra.y, ra.z, ra.w};
            float bv[4] = {rb.x, rb.y, rb.z, rb.w};
            #pragma unroll
            for (int i = 0; i < 4; i++)
                #pragma unroll
                for (int j = 0; j < 4; j++)
                    acc[i][j] += av[i] * bv[j];
        }
        __syncthreads();
    }
    #pragma unroll
    for (int i = 0; i < 4; i++) {
        int m = m0 + (ty << 2) + i;
        #pragma unroll
        for (int j = 0; j < 4; j++) {
            int n = n0 + (tx << 2) + j;
            C[(size_t)m * N + n] = acc[i][j] * scale;
        }
    }
}

// ---------------------------------------------------------------------------
// Top-k + softmax + sparse AV + attn row write — atomic-free heavy path
// ---------------------------------------------------------------------------
__device__ __forceinline__ unsigned encf(float x) {
    unsigned u = __float_as_uint(x);
    return (u & 0x80000000u) ? ~u : (u | 0x80000000u);
}
__device__ __forceinline__ float decf(unsigned u) {
    return (u & 0x80000000u) ? __uint_as_float(u ^ 0x80000000u) : __uint_as_float(~u);
}
__device__ __forceinline__ int warp_incl_scan(int v, int lane) {
    #pragma unroll
    for (int o = 1; o < 32; o <<= 1) {
        int n = __shfl_up_sync(0xffffffffu, v, o);
        if (lane >= o) v += n;
    }
    return v;
}
__device__ __forceinline__ int ballot_append(bool flag, int* counter, int lane) {
    unsigned m = __ballot_sync(0xffffffffu, flag);
    int base = 0;
    if (m) {
        int leader = __ffs(m) - 1;
        if (lane == leader) base = atomicAdd(counter, __popc(m));
        base = __shfl_sync(0xffffffffu, base, leader);
    }
    return base + __popc(m & ((1u << lane) - 1u));
}
// digit pick over 4 warp-private 256-bin hists
__device__ __forceinline__ void pick_digit_mw(
    const int wh[4][256], int kk, int tid, int lane, int wid,
    int* wtot, int* s_d, int* s_k)
{
    int b0 = 2 * tid, b1 = 2 * tid + 1;
    int h0 = wh[0][b0] + wh[1][b0] + wh[2][b0] + wh[3][b0];
    int h1 = wh[0][b1] + wh[1][b1] + wh[2][b1] + wh[3][b1];
    int ps = h0 + h1;
    int incl = warp_incl_scan(ps, lane);
    if (lane == 31) wtot[wid] = incl;
    __syncthreads();
    int base = 0;
    #pragma unroll
    for (int w2 = 0; w2 < 4; w2++) if (w2 < wid) base += wtot[w2];
    int Tot = wtot[0] + wtot[1] + wtot[2] + wtot[3];
    int inclAll = incl + base;
    int S0 = Tot - inclAll + ps;     // suffix sum from bin b0
    int S1 = S0 - h0;                // suffix from b1
    int S2 = S0 - ps;                // suffix from b1+1
    if (S0 >= kk && S1 < kk) { *s_d = b0; *s_k = kk - S1; }
    if (S1 >= kk && S2 < kk) { *s_d = b1; *s_k = kk - S2; }
    __syncthreads();
}

__global__ __launch_bounds__(128) void topk_attn_kernel(
    const float* __restrict__ logits, const float* __restrict__ vp,
    float* __restrict__ mix, float* __restrict__ attn, int write_attn)
{
    const int row = blockIdx.x;
    const int bh  = row >> 11;
    const int qi  = row & 2047;
    const int b   = bh >> 4;
    const int h   = bh & 15;
    const int tid = threadIdx.x;
    const int lane = tid & 31;
    const int wid  = tid >> 5;
    const unsigned ltm = (1u << lane) - 1u;

    __shared__ unsigned su[LK_];      // 8KB
    __shared__ int      cand[LK_];    // 8KB (worst case)
    __shared__ int      whist[4][256];// 4KB per-warp hists
    __shared__ int      ggt[16], geq[16];
    __shared__ int      wtot[4];
    __shared__ unsigned wmax[4];
    __shared__ float    wsum[2];
    __shared__ int      sel_idx[TOPK_];
    __shared__ float    sel_w[TOPK_];
    __shared__ float    sred[128];
    __shared__ int      s_d, s_k, s_nsel, s_ncand;
    __shared__ float    s_max, s_invZ;

    // RACE FIX (R7 bug): each warp zeros ONLY ITS OWN histogram row.
    // In-warp program order then guarantees zero-before-atomicAdd; other
    // warps read the row only after the __syncthreads() below.
    #pragma unroll
    for (int j = 0; j < 8; j++) whist[wid][lane + j * 32] = 0;

    // --- Load row, encode keys (kept in regs), rowmax ---
    const float4* lrow4 = (const float4*)(logits + (size_t)row * LK_);
    unsigned ee[16];
    unsigned lm = 0u;
    #pragma unroll
    for (int it = 0; it < 4; it++) {
        int i4 = tid + it * 128;
        float4 x = lrow4[i4];
        unsigned e0 = encf(x.x), e1 = encf(x.y), e2 = encf(x.z), e3 = encf(x.w);
        ee[it*4+0] = e0; ee[it*4+1] = e1; ee[it*4+2] = e2; ee[it*4+3] = e3;
        ((uint4*)su)[i4] = make_uint4(e0, e1, e2, e3);
        unsigned m01 = e0 > e1 ? e0 : e1;
        unsigned m23 = e2 > e3 ? e2 : e3;
        unsigned m = m01 > m23 ? m01 : m23;
        lm = lm > m ? lm : m;
    }
    #pragma unroll
    for (int o = 16; o > 0; o >>= 1) {
        unsigned v = __shfl_xor_sync(0xffffffffu, lm, o);
        lm = lm > v ? lm : v;
    }
    if (lane == 0) wmax[wid] = lm;

    // pass-1 hist: per-warp private row, match-aggregated
    #pragma unroll
    for (int j = 0; j < 16; j++) {
        int dg = (int)(ee[j] >> 24);
        unsigned mm = __match_any_sync(0xffffffffu, dg);
        if ((int)(__ffs(mm) - 1) == lane) atomicAdd(&whist[wid][dg], __popc(mm));
    }
    __syncthreads();
    if (tid == 0) {
        unsigned m = wmax[0];
        m = m > wmax[1] ? m : wmax[1];
        m = m > wmax[2] ? m : wmax[2];
        m = m > wmax[3] ? m : wmax[3];
        s_max = decf(m);
    }
    pick_digit_mw(whist, TOPK_, tid, lane, wid, wtot, &s_d, &s_k);
    const float rowmax = s_max;
    const int d1 = s_d;
    int kk = s_k;

    // --- Pass-1 compaction: ballot/group-count scan, NO atomics ---
    // element i = 4*tid + 512*it + c -> group g = 4*it + wid (base 512*it+128*wid),
    // in-group offset 4*lane + c (monotone in index).
    #pragma unroll
    for (int it = 0; it < 4; it++) {
        int cg = 0, ce = 0;
        #pragma unroll
        for (int c = 0; c < 4; c++) {
            int dg = (int)(ee[it*4+c] >> 24);
            unsigned mg = __ballot_sync(0xffffffffu, dg > d1);
            unsigned me = __ballot_sync(0xffffffffu, dg == d1);
            cg += __popc(mg); ce += __popc(me);
        }
        if (lane == 0) { ggt[it*4+wid] = cg; geq[it*4+wid] = ce; }
    }
    __syncthreads();
    int basegt[4], baseeq[4];
    {
        int rg = 0, re = 0;
        #pragma unroll
        for (int g = 0; g < 16; g++) {
            if ((g & 3) == wid) { basegt[g >> 2] = rg; baseeq[g >> 2] = re; }
            rg += ggt[g]; re += geq[g];
        }
        if (tid == 0) { s_nsel = rg; s_ncand = re; }
    }
    // write-out (recompute ballots; rank = lanes-below(all c) + same-lane earlier c)
    #pragma unroll
    for (int it = 0; it < 4; it++) {
        unsigned mg[4], me[4];
        #pragma unroll
        for (int c = 0; c < 4; c++) {
            int dg = (int)(ee[it*4+c] >> 24);
            mg[c] = __ballot_sync(0xffffffffu, dg > d1);
            me[c] = __ballot_sync(0xffffffffu, dg == d1);
        }
        int belowg = __popc(mg[0]&ltm) + __popc(mg[1]&ltm) + __popc(mg[2]&ltm) + __popc(mg[3]&ltm);
        int belowe = __popc(me[0]&ltm) + __popc(me[1]&ltm) + __popc(me[2]&ltm) + __popc(me[3]&ltm);
        int sg = 0, se = 0;
        #pragma unroll
        for (int c = 0; c < 4; c++) {
            int i = 4*tid + 512*it + c;
            bool isg = (mg[c] >> lane) & 1u;
            bool ise = (me[c] >> lane) & 1u;
            if (isg) sel_idx[basegt[it] + belowg + sg] = i;
            if (ise) cand[baseeq[it] + belowe + se] = i;
            sg += isg; se += ise;
        }
    }
    __syncthreads();
    int C = s_ncand;

    // --- Passes 2..4 on shrinking candidate list (small; atomics OK) ---
    for (int shift = 16; shift >= 0 && C > kk; shift -= 8) {
        #pragma unroll
        for (int j = 0; j < 8; j++) whist[wid][lane + j * 32] = 0;
        __syncthreads();
        for (int c = tid; c < C; c += 128)
            atomicAdd(&whist[wid][(su[cand[c]] >> shift) & 255u], 1);
        __syncthreads();
        pick_digit_mw(whist, kk, tid, lane, wid, wtot, &s_d, &s_k);
        int d = s_d;
        int mine[16]; int nm = 0;
        for (int c = tid; c < C; c += 128) mine[nm++] = cand[c];
        __syncthreads();
        if (tid == 0) s_ncand = 0;
        __syncthreads();
        int Cpad = (C + 127) & ~127;
        int used = 0;
        for (int c0 = 0; c0 < Cpad; c0 += 128) {
            int c = c0 + tid;
            bool active = (c < C);
            int idx = active ? mine[used] : 0;
            if (active) used++;
            int dg = active ? (int)((su[idx] >> shift) & 255u) : -1;
            bool is_g = active && (dg > d);
            bool is_e = active && (dg == d);
            int pg = ballot_append(is_g, &s_nsel, lane);
            if (is_g) sel_idx[pg] = idx;
            int pe = ballot_append(is_e, &s_ncand, lane);
            if (is_e) cand[pe] = idx;
        }
        __syncthreads();
        C = s_ncand;
        kk = s_k;
    }

    // --- Finish (ties by lowest index, jax semantics) ---
    if (C == kk) {
        for (int c = tid; c < C; c += 128) {
            int pos = atomicAdd(&s_nsel, 1);
            sel_idx[pos] = cand[c];
        }
    } else {
        for (int c = tid; c < C; c += 128) {
            int idx = cand[c];
            int r = 0;
            for (int j = 0; j < C; j++) r += (cand[j] < idx);
            if (r < kk) { int pos = atomicAdd(&s_nsel, 1); sel_idx[pos] = idx; }
        }
    }
    __syncthreads();

    // --- Softmax over the 64 selected ---
    float w = 0.f;
    if (tid < TOPK_) {
        w = expf(decf(su[sel_idx[tid]]) - rowmax);
        sel_w[tid] = w;
    }
    float zl = w;
    #pragma unroll
    for (int o = 16; o > 0; o >>= 1) zl += __shfl_xor_sync(0xffffffffu, zl, o);
    if (tid < TOPK_ && lane == 0) wsum[wid] = zl;
    __syncthreads();
    if (tid == 0) s_invZ = 1.0f / (wsum[0] + wsum[1]);
    __syncthreads();
    const float invZ = s_invZ;
    if (tid < TOPK_) sel_w[tid] = sel_w[tid] * invZ;
    __syncthreads();

    // --- Build full attn row in smem (reuse su) and stream out coalesced ---
    if (write_attn) {
        float4* s4 = (float4*)su;
        const float4 z4 = make_float4(0.f, 0.f, 0.f, 0.f);
        #pragma unroll
        for (int it = 0; it < 4; it++) s4[tid + it * 128] = z4;
        __syncthreads();
        if (tid < TOPK_) ((float*)su)[sel_idx[tid]] = sel_w[tid];
        __syncthreads();
        float4* arow4 = (float4*)(attn + (size_t)row * LK_);
        #pragma unroll
        for (int it = 0; it < 4; it++) arow4[tid + it * 128] = s4[tid + it * 128];
    }

    // --- Sparse AV ---
    {
        const int d = tid & 63, half = tid >> 6;
        const float* vb = vp + (size_t)bh * LK_ * 64;
        float accv = 0.f;
        for (int s = half; s < TOPK_; s += 2)
            accv += sel_w[s] * vb[(size_t)sel_idx[s] * 64 + d];
        sred[tid] = accv;
        __syncthreads();
        if (tid < 64)
            mix[((size_t)(b * LQ_ + qi)) * (HH * DVV) + h * 64 + tid] =
                sred[tid] + sred[tid + 64];
    }
}

// ---------------------------------------------------------------------------
extern "C" void kernel_launch(void* const* d_in, const int* in_sizes, int n_in,
                              void* d_out, int out_size) {
    (void)in_sizes; (void)n_in;
    const float* q    = (const float*)d_in[0];
    const float* k    = (const float*)d_in[1];
    const float* v    = (const float*)d_in[2];
    const float* w_qs = (const float*)d_in[3];
    const float* w_ks = (const float*)d_in[4];
    const float* w_vs = (const float*)d_in[5];
    const float* fc   = (const float*)d_in[6];
    float* out = (float*)d_out;

    float *qp, *kp, *vp, *mix, *lg;
    cudaGetSymbolAddress((void**)&qp,  g_qp);
    cudaGetSymbolAddress((void**)&kp,  g_kp);
    cudaGetSymbolAddress((void**)&vp,  g_vp);
    cudaGetSymbolAddress((void**)&mix, g_mix);
    cudaGetSymbolAddress((void**)&lg,  g_logits);

    const long long out_elems  = (long long)BB * LQ_ * DVV;           // 262144
    const long long attn_elems = (long long)BB * HH * LQ_ * LK_;      // 134217728
    int write_attn = ((long long)out_size >= out_elems + attn_elems) ? 1 : 0;
    float* attn = out + out_elems;

    dim3 blk(256);
    // QP = (q @ w_qs^T) * 0.125
    sgemm128<<<dim3(8, 32, 1), blk>>>(q, w_qs, qp, BB*LQ_, HH*DKK, EE, 0, 0.125f, LQ_, 0, 0, 0);
    // KP = k @ w_ks^T
    sgemm128<<<dim3(8, 32, 1), blk>>>(k, w_ks, kp, BB*LK_, HH*DKK, EE, 0, 1.0f, LK_, 0, 0, 0);
    // VP = v @ w_vs^T
    sgemm128<<<dim3(8, 32, 1), blk>>>(v, w_vs, vp, BB*LK_, HH*DVV, DVV, 0, 1.0f, LK_, 0, 0, 0);
    // logits[bh] = QP[bh] @ KP[bh]^T
    sgemm128<<<dim3(16, 16, BB*HH), blk>>>(qp, kp, lg, LQ_, LK_, DKK, 1, 1.0f, 0,
                                           (size_t)LQ_ * DKK, (size_t)LK_ * DKK,
                                           (size_t)LQ_ * LK_);

    topk_attn_kernel<<<BB * HH * LQ_, 128>>>(lg, vp, mix, attn, write_attn);

    // out = mix @ fc^T
    sgemm_nt<<<dim3(1, 64, 1), blk>>>(mix, fc, out, BB*LQ_, DVV, HH*DVV, 1.0f);
}

// round 9
// speedup vs baseline: 1.4488x; 1.0208x over previous
#include <cuda_runtime.h>
#include <cuda_bf16.h>
#include <math.h>

// Problem constants
#define BB    2
#define LQ_   2048
#define LK_   2048
#define EE    1024
#define HH    16
#define DKK   64
#define DVV   64
#define TOPK_ 64

// Device scratch
__device__ __align__(256) float g_qp[BB*HH*LQ_*DKK];
__device__ __align__(256) float g_kp[BB*HH*LK_*DKK];
__device__ __align__(256) float g_vp[BB*HH*LK_*DVV];
__device__ __align__(256) float g_mix[BB*LQ_*HH*DVV];
__device__ __align__(256) float g_logits[(size_t)BB*HH*LQ_*LK_]; // 512MB

// --------------------------- f32x2 helpers --------------------------------
typedef unsigned long long ull;
__device__ __forceinline__ ull dup2(float x) {
    ull r; asm("mov.b64 %0, {%1, %1};" : "=l"(r) : "f"(x)); return r;
}
__device__ __forceinline__ ull fma2(ull a, ull b, ull c) {
    ull d; asm("fma.rn.f32x2 %0, %1, %2, %3;" : "=l"(d) : "l"(a), "l"(b), "l"(c)); return d;
}
__device__ __forceinline__ float2 unp2(ull p) {
    float2 f; asm("mov.b64 {%0, %1}, %2;" : "=f"(f.x), "=f"(f.y) : "l"(p)); return f;
}

// ---------------------------------------------------------------------------
// Merged projection GEMM: z selects (A, W, C, K, scale).  All share
// M=4096, N=1024, mode-0 scatter with Lrows=2048.
// 128x128 tile, 8x8 micro-tile, f32x2 FMA, double-buffered smem.
// ---------------------------------------------------------------------------
struct ProjArgs {
    const float* A[3];
    const float* W[3];
    float*       C[3];
    int          K[3];
    float        scale[3];
};

__global__ void __launch_bounds__(256, 2) proj_gemm(ProjArgs pa)
{
    const int z = blockIdx.z;
    const float* __restrict__ A = pa.A[z];
    const float* __restrict__ W = pa.W[z];
    float* __restrict__ C = pa.C[z];
    const int K = pa.K[z];
    const float scale = pa.scale[z];

    const int m0 = blockIdx.y * 128;
    const int n0 = blockIdx.x * 128;
    const int tid = threadIdx.x;
    const int ty = tid >> 4;
    const int tx = tid & 15;
    const int lr = tid >> 1;
    const int lc = (tid & 1) << 2;

    __shared__ __align__(16) float As[2][8][132];
    __shared__ __align__(16) float Ws[2][8][132];

    ull accp[8][4];
    #pragma unroll
    for (int i = 0; i < 8; i++)
        #pragma unroll
        for (int j = 0; j < 4; j++) accp[i][j] = 0ull;

    const float* Arow = A + (size_t)(m0 + lr) * K + lc;
    const float* Wrow = W + (size_t)(n0 + lr) * K + lc;
    {
        float4 a = *(const float4*)(Arow);
        float4 w = *(const float4*)(Wrow);
        As[0][lc+0][lr] = a.x; As[0][lc+1][lr] = a.y; As[0][lc+2][lr] = a.z; As[0][lc+3][lr] = a.w;
        Ws[0][lc+0][lr] = w.x; Ws[0][lc+1][lr] = w.y; Ws[0][lc+2][lr] = w.z; Ws[0][lc+3][lr] = w.w;
    }
    __syncthreads();

    const int nT = K >> 3;
    for (int t = 0; t < nT; t++) {
        const int cur = t & 1;
        float4 an, wn;
        const bool more = (t + 1 < nT);
        if (more) {
            an = *(const float4*)(Arow + (t + 1) * 8);
            wn = *(const float4*)(Wrow + (t + 1) * 8);
        }
        #pragma unroll
        for (int e = 0; e < 8; e++) {
            float4 a0 = *(const float4*)&As[cur][e][ty * 8];
            float4 a1 = *(const float4*)&As[cur][e][ty * 8 + 4];
            ulonglong2 bp0 = *(const ulonglong2*)&Ws[cur][e][tx * 8];
            ulonglong2 bp1 = *(const ulonglong2*)&Ws[cur][e][tx * 8 + 4];
            ull bv[4] = {bp0.x, bp0.y, bp1.x, bp1.y};
            float av[8] = {a0.x, a0.y, a0.z, a0.w, a1.x, a1.y, a1.z, a1.w};
            #pragma unroll
            for (int i = 0; i < 8; i++) {
                ull ad = dup2(av[i]);
                #pragma unroll
                for (int j = 0; j < 4; j++)
                    accp[i][j] = fma2(ad, bv[j], accp[i][j]);
            }
        }
        if (more) {
            const int nxt = cur ^ 1;
            As[nxt][lc+0][lr] = an.x; As[nxt][lc+1][lr] = an.y;
            As[nxt][lc+2][lr] = an.z; As[nxt][lc+3][lr] = an.w;
            Ws[nxt][lc+0][lr] = wn.x; Ws[nxt][lc+1][lr] = wn.y;
            Ws[nxt][lc+2][lr] = wn.z; Ws[nxt][lc+3][lr] = wn.w;
            __syncthreads();
        }
    }

    // mode-0 scatter: n=(h*64+d), m=(b*2048+l) -> [(b*16+h)*2048+l]*64+d
    #pragma unroll
    for (int i = 0; i < 8; i++) {
        int m = m0 + ty * 8 + i;
        int b = m >> 11, l = m & 2047;
        #pragma unroll
        for (int j2 = 0; j2 < 2; j2++) {
            float2 p0 = unp2(accp[i][j2*2+0]);
            float2 p1 = unp2(accp[i][j2*2+1]);
            float4 o = make_float4(p0.x*scale, p0.y*scale, p1.x*scale, p1.y*scale);
            int n = n0 + tx * 8 + j2 * 4;
            int h = n >> 6, d = n & 63;
            *(float4*)&C[(((size_t)b * HH + h) * 2048 + l) * 64 + d] = o;
        }
    }
}

// ---------------------------------------------------------------------------
// Batched logits GEMM (row-major out), 128x128 tile, 8x8 micro, f32x2.
// ---------------------------------------------------------------------------
__global__ void __launch_bounds__(256, 2) sgemm128(
    const float* __restrict__ A, const float* __restrict__ W, float* __restrict__ C,
    int K, size_t sA, size_t sW, size_t sC)
{
    A += (size_t)blockIdx.z * sA;
    W += (size_t)blockIdx.z * sW;
    C += (size_t)blockIdx.z * sC;
    const int m0 = blockIdx.y * 128;
    const int n0 = blockIdx.x * 128;
    const int tid = threadIdx.x;
    const int ty = tid >> 4;
    const int tx = tid & 15;
    const int lr = tid >> 1;
    const int lc = (tid & 1) << 2;
    const int N = LK_;

    __shared__ __align__(16) float As[2][8][132];
    __shared__ __align__(16) float Ws[2][8][132];

    ull accp[8][4];
    #pragma unroll
    for (int i = 0; i < 8; i++)
        #pragma unroll
        for (int j = 0; j < 4; j++) accp[i][j] = 0ull;

    const float* Arow = A + (size_t)(m0 + lr) * K + lc;
    const float* Wrow = W + (size_t)(n0 + lr) * K + lc;
    {
        float4 a = *(const float4*)(Arow);
        float4 w = *(const float4*)(Wrow);
        As[0][lc+0][lr] = a.x; As[0][lc+1][lr] = a.y; As[0][lc+2][lr] = a.z; As[0][lc+3][lr] = a.w;
        Ws[0][lc+0][lr] = w.x; Ws[0][lc+1][lr] = w.y; Ws[0][lc+2][lr] = w.z; Ws[0][lc+3][lr] = w.w;
    }
    __syncthreads();

    const int nT = K >> 3;
    for (int t = 0; t < nT; t++) {
        const int cur = t & 1;
        float4 an, wn;
        const bool more = (t + 1 < nT);
        if (more) {
            an = *(const float4*)(Arow + (t + 1) * 8);
            wn = *(const float4*)(Wrow + (t + 1) * 8);
        }
        #pragma unroll
        for (int e = 0; e < 8; e++) {
            float4 a0 = *(const float4*)&As[cur][e][ty * 8];
            float4 a1 = *(const float4*)&As[cur][e][ty * 8 + 4];
            ulonglong2 bp0 = *(const ulonglong2*)&Ws[cur][e][tx * 8];
            ulonglong2 bp1 = *(const ulonglong2*)&Ws[cur][e][tx * 8 + 4];
            ull bv[4] = {bp0.x, bp0.y, bp1.x, bp1.y};
            float av[8] = {a0.x, a0.y, a0.z, a0.w, a1.x, a1.y, a1.z, a1.w};
            #pragma unroll
            for (int i = 0; i < 8; i++) {
                ull ad = dup2(av[i]);
                #pragma unroll
                for (int j = 0; j < 4; j++)
                    accp[i][j] = fma2(ad, bv[j], accp[i][j]);
            }
        }
        if (more) {
            const int nxt = cur ^ 1;
            As[nxt][lc+0][lr] = an.x; As[nxt][lc+1][lr] = an.y;
            As[nxt][lc+2][lr] = an.z; As[nxt][lc+3][lr] = an.w;
            Ws[nxt][lc+0][lr] = wn.x; Ws[nxt][lc+1][lr] = wn.y;
            Ws[nxt][lc+2][lr] = wn.z; Ws[nxt][lc+3][lr] = wn.w;
            __syncthreads();
        }
    }

    #pragma unroll
    for (int i = 0; i < 8; i++) {
        int m = m0 + ty * 8 + i;
        #pragma unroll
        for (int j2 = 0; j2 < 2; j2++) {
            float2 p0 = unp2(accp[i][j2*2+0]);
            float2 p1 = unp2(accp[i][j2*2+1]);
            float4 o = make_float4(p0.x, p0.y, p1.x, p1.y);
            int n = n0 + tx * 8 + j2 * 4;
            *(float4*)&C[(size_t)m * N + n] = o;
        }
    }
}

// ---------------------------------------------------------------------------
// Small GEMM kept for fc (N=64): C = A*W^T, 64x64 tile, 4x4 micro.
// ---------------------------------------------------------------------------
__global__ __launch_bounds__(256) void sgemm_nt(
    const float* __restrict__ A, const float* __restrict__ W, float* __restrict__ C,
    int M, int N, int K, float scale)
{
    const int m0 = blockIdx.y * 64;
    const int n0 = blockIdx.x * 64;
    const int tid = threadIdx.x;
    const int ty = tid >> 4;
    const int tx = tid & 15;

    __shared__ __align__(16) float As[32][68];
    __shared__ __align__(16) float Ws[32][68];

    float acc[4][4];
    #pragma unroll
    for (int i = 0; i < 4; i++)
        #pragma unroll
        for (int j = 0; j < 4; j++) acc[i][j] = 0.f;

    for (int kt = 0; kt < K; kt += 32) {
        #pragma unroll
        for (int i = 0; i < 2; i++) {
            int f  = tid + i * 256;
            int r  = f >> 3;
            int c4 = (f & 7) << 2;
            float4 a = *(const float4*)(A + (size_t)(m0 + r) * K + kt + c4);
            As[c4+0][r] = a.x; As[c4+1][r] = a.y; As[c4+2][r] = a.z; As[c4+3][r] = a.w;
            float4 w = *(const float4*)(W + (size_t)(n0 + r) * K + kt + c4);
            Ws[c4+0][r] = w.x; Ws[c4+1][r] = w.y; Ws[c4+2][r] = w.z; Ws[c4+3][r] = w.w;
        }
        __syncthreads();
        #pragma unroll
        for (int e = 0; e < 32; e++) {
            float4 ra = *(const float4*)&As[e][ty << 2];
            float4 rb = *(const float4*)&Ws[e][tx << 2];
            float av[4] = {ra.x, ra.y, ra.z, ra.w};
            float bv[4] = {rb.x, rb.y, rb.z, rb.w};
            #pragma unroll
            for (int i = 0; i < 4; i++)
                #pragma unroll
                for (int j = 0; j < 4; j++)
                    acc[i][j] += av[i] * bv[j];
        }
        __syncthreads();
    }
    #pragma unroll
    for (int i = 0; i < 4; i++) {
        int m = m0 + (ty << 2) + i;
        #pragma unroll
        for (int j = 0; j < 4; j++) {
            int n = n0 + (tx << 2) + j;
            C[(size_t)m * N + n] = acc[i][j] * scale;
        }
    }
}

// Tiny no-op kernel: shifts launch ordering so ncu's -s 5 -c 1 window lands
// on topk_attn_kernel (instrumentation only; ~1us each, deterministic).
__global__ void noop_kernel() {}

// ---------------------------------------------------------------------------
// Top-k + softmax + sparse AV + attn row write (R8, passing)
// ---------------------------------------------------------------------------
__device__ __forceinline__ unsigned encf(float x) {
    unsigned u = __float_as_uint(x);
    return (u & 0x80000000u) ? ~u : (u | 0x80000000u);
}
__device__ __forceinline__ float decf(unsigned u) {
    return (u & 0x80000000u) ? __uint_as_float(u ^ 0x80000000u) : __uint_as_float(~u);
}
__device__ __forceinline__ int warp_incl_scan(int v, int lane) {
    #pragma unroll
    for (int o = 1; o < 32; o <<= 1) {
        int n = __shfl_up_sync(0xffffffffu, v, o);
        if (lane >= o) v += n;
    }
    return v;
}
__device__ __forceinline__ int ballot_append(bool flag, int* counter, int lane) {
    unsigned m = __ballot_sync(0xffffffffu, flag);
    int base = 0;
    if (m) {
        int leader = __ffs(m) - 1;
        if (lane == leader) base = atomicAdd(counter, __popc(m));
        base = __shfl_sync(0xffffffffu, base, leader);
    }
    return base + __popc(m & ((1u << lane) - 1u));
}
__device__ __forceinline__ void pick_digit_mw(
    const int wh[4][256], int kk, int tid, int lane, int wid,
    int* wtot, int* s_d, int* s_k)
{
    int b0 = 2 * tid, b1 = 2 * tid + 1;
    int h0 = wh[0][b0] + wh[1][b0] + wh[2][b0] + wh[3][b0];
    int h1 = wh[0][b1] + wh[1][b1] + wh[2][b1] + wh[3][b1];
    int ps = h0 + h1;
    int incl = warp_incl_scan(ps, lane);
    if (lane == 31) wtot[wid] = incl;
    __syncthreads();
    int base = 0;
    #pragma unroll
    for (int w2 = 0; w2 < 4; w2++) if (w2 < wid) base += wtot[w2];
    int Tot = wtot[0] + wtot[1] + wtot[2] + wtot[3];
    int inclAll = incl + base;
    int S0 = Tot - inclAll + ps;
    int S1 = S0 - h0;
    int S2 = S0 - ps;
    if (S0 >= kk && S1 < kk) { *s_d = b0; *s_k = kk - S1; }
    if (S1 >= kk && S2 < kk) { *s_d = b1; *s_k = kk - S2; }
    __syncthreads();
}

__global__ __launch_bounds__(128) void topk_attn_kernel(
    const float* __restrict__ logits, const float* __restrict__ vp,
    float* __restrict__ mix, float* __restrict__ attn, int write_attn)
{
    const int row = blockIdx.x;
    const int bh  = row >> 11;
    const int qi  = row & 2047;
    const int b   = bh >> 4;
    const int h   = bh & 15;
    const int tid = threadIdx.x;
    const int lane = tid & 31;
    const int wid  = tid >> 5;
    const unsigned ltm = (1u << lane) - 1u;

    __shared__ unsigned su[LK_];
    __shared__ int      cand[LK_];
    __shared__ int      whist[4][256];
    __shared__ int      ggt[16], geq[16];
    __shared__ int      wtot[4];
    __shared__ unsigned wmax[4];
    __shared__ float    wsum[2];
    __shared__ int      sel_idx[TOPK_];
    __shared__ float    sel_w[TOPK_];
    __shared__ float    sred[128];
    __shared__ int      s_d, s_k, s_nsel, s_ncand;
    __shared__ float    s_max, s_invZ;

    // each warp zeros ONLY ITS OWN histogram row (race-free by program order)
    #pragma unroll
    for (int j = 0; j < 8; j++) whist[wid][lane + j * 32] = 0;

    const float4* lrow4 = (const float4*)(logits + (size_t)row * LK_);
    unsigned ee[16];
    unsigned lm = 0u;
    #pragma unroll
    for (int it = 0; it < 4; it++) {
        int i4 = tid + it * 128;
        float4 x = lrow4[i4];
        unsigned e0 = encf(x.x), e1 = encf(x.y), e2 = encf(x.z), e3 = encf(x.w);
        ee[it*4+0] = e0; ee[it*4+1] = e1; ee[it*4+2] = e2; ee[it*4+3] = e3;
        ((uint4*)su)[i4] = make_uint4(e0, e1, e2, e3);
        unsigned m01 = e0 > e1 ? e0 : e1;
        unsigned m23 = e2 > e3 ? e2 : e3;
        unsigned m = m01 > m23 ? m01 : m23;
        lm = lm > m ? lm : m;
    }
    #pragma unroll
    for (int o = 16; o > 0; o >>= 1) {
        unsigned v = __shfl_xor_sync(0xffffffffu, lm, o);
        lm = lm > v ? lm : v;
    }
    if (lane == 0) wmax[wid] = lm;

    #pragma unroll
    for (int j = 0; j < 16; j++) {
        int dg = (int)(ee[j] >> 24);
        unsigned mm = __match_any_sync(0xffffffffu, dg);
        if ((int)(__ffs(mm) - 1) == lane) atomicAdd(&whist[wid][dg], __popc(mm));
    }
    __syncthreads();
    if (tid == 0) {
        unsigned m = wmax[0];
        m = m > wmax[1] ? m : wmax[1];
        m = m > wmax[2] ? m : wmax[2];
        m = m > wmax[3] ? m : wmax[3];
        s_max = decf(m);
    }
    pick_digit_mw(whist, TOPK_, tid, lane, wid, wtot, &s_d, &s_k);
    const float rowmax = s_max;
    const int d1 = s_d;
    int kk = s_k;

    #pragma unroll
    for (int it = 0; it < 4; it++) {
        int cg = 0, ce = 0;
        #pragma unroll
        for (int c = 0; c < 4; c++) {
            int dg = (int)(ee[it*4+c] >> 24);
            unsigned mg = __ballot_sync(0xffffffffu, dg > d1);
            unsigned me = __ballot_sync(0xffffffffu, dg == d1);
            cg += __popc(mg); ce += __popc(me);
        }
        if (lane == 0) { ggt[it*4+wid] = cg; geq[it*4+wid] = ce; }
    }
    __syncthreads();
    int basegt[4], baseeq[4];
    {
        int rg = 0, re = 0;
        #pragma unroll
        for (int g = 0; g < 16; g++) {
            if ((g & 3) == wid) { basegt[g >> 2] = rg; baseeq[g >> 2] = re; }
            rg += ggt[g]; re += geq[g];
        }
        if (tid == 0) { s_nsel = rg; s_ncand = re; }
    }
    #pragma unroll
    for (int it = 0; it < 4; it++) {
        unsigned mg[4], me[4];
        #pragma unroll
        for (int c = 0; c < 4; c++) {
            int dg = (int)(ee[it*4+c] >> 24);
            mg[c] = __ballot_sync(0xffffffffu, dg > d1);
            me[c] = __ballot_sync(0xffffffffu, dg == d1);
        }
        int belowg = __popc(mg[0]&ltm) + __popc(mg[1]&ltm) + __popc(mg[2]&ltm) + __popc(mg[3]&ltm);
        int belowe = __popc(me[0]&ltm) + __popc(me[1]&ltm) + __popc(me[2]&ltm) + __popc(me[3]&ltm);
        int sg = 0, se = 0;
        #pragma unroll
        for (int c = 0; c < 4; c++) {
            int i = 4*tid + 512*it + c;
            bool isg = (mg[c] >> lane) & 1u;
            bool ise = (me[c] >> lane) & 1u;
            if (isg) sel_idx[basegt[it] + belowg + sg] = i;
            if (ise) cand[baseeq[it] + belowe + se] = i;
            sg += isg; se += ise;
        }
    }
    __syncthreads();
    int C = s_ncand;

    for (int shift = 16; shift >= 0 && C > kk; shift -= 8) {
        #pragma unroll
        for (int j = 0; j < 8; j++) whist[wid][lane + j * 32] = 0;
        __syncthreads();
        for (int c = tid; c < C; c += 128)
            atomicAdd(&whist[wid][(su[cand[c]] >> shift) & 255u], 1);
        __syncthreads();
        pick_digit_mw(whist, kk, tid, lane, wid, wtot, &s_d, &s_k);
        int d = s_d;
        int mine[16]; int nm = 0;
        for (int c = tid; c < C; c += 128) mine[nm++] = cand[c];
        __syncthreads();
        if (tid == 0) s_ncand = 0;
        __syncthreads();
        int Cpad = (C + 127) & ~127;
        int used = 0;
        for (int c0 = 0; c0 < Cpad; c0 += 128) {
            int c = c0 + tid;
            bool active = (c < C);
            int idx = active ? mine[used] : 0;
            if (active) used++;
            int dg = active ? (int)((su[idx] >> shift) & 255u) : -1;
            bool is_g = active && (dg > d);
            bool is_e = active && (dg == d);
            int pg = ballot_append(is_g, &s_nsel, lane);
            if (is_g) sel_idx[pg] = idx;
            int pe = ballot_append(is_e, &s_ncand, lane);
            if (is_e) cand[pe] = idx;
        }
        __syncthreads();
        C = s_ncand;
        kk = s_k;
    }

    if (C == kk) {
        for (int c = tid; c < C; c += 128) {
            int pos = atomicAdd(&s_nsel, 1);
            sel_idx[pos] = cand[c];
        }
    } else {
        for (int c = tid; c < C; c += 128) {
            int idx = cand[c];
            int r = 0;
            for (int j = 0; j < C; j++) r += (cand[j] < idx);
            if (r < kk) { int pos = atomicAdd(&s_nsel, 1); sel_idx[pos] = idx; }
        }
    }
    __syncthreads();

    float w = 0.f;
    if (tid < TOPK_) {
        w = expf(decf(su[sel_idx[tid]]) - rowmax);
        sel_w[tid] = w;
    }
    float zl = w;
    #pragma unroll
    for (int o = 16; o > 0; o >>= 1) zl += __shfl_xor_sync(0xffffffffu, zl, o);
    if (tid < TOPK_ && lane == 0) wsum[wid] = zl;
    __syncthreads();
    if (tid == 0) s_invZ = 1.0f / (wsum[0] + wsum[1]);
    __syncthreads();
    const float invZ = s_invZ;
    if (tid < TOPK_) sel_w[tid] = sel_w[tid] * invZ;
    __syncthreads();

    if (write_attn) {
        float4* s4 = (float4*)su;
        const float4 z4 = make_float4(0.f, 0.f, 0.f, 0.f);
        #pragma unroll
        for (int it = 0; it < 4; it++) s4[tid + it * 128] = z4;
        __syncthreads();
        if (tid < TOPK_) ((float*)su)[sel_idx[tid]] = sel_w[tid];
        __syncthreads();
        float4* arow4 = (float4*)(attn + (size_t)row * LK_);
        #pragma unroll
        for (int it = 0; it < 4; it++) arow4[tid + it * 128] = s4[tid + it * 128];
    }

    {
        const int d = tid & 63, half = tid >> 6;
        const float* vb = vp + (size_t)bh * LK_ * 64;
        float accv = 0.f;
        for (int s = half; s < TOPK_; s += 2)
            accv += sel_w[s] * vb[(size_t)sel_idx[s] * 64 + d];
        sred[tid] = accv;
        __syncthreads();
        if (tid < 64)
            mix[((size_t)(b * LQ_ + qi)) * (HH * DVV) + h * 64 + tid] =
                sred[tid] + sred[tid + 64];
    }
}

// ---------------------------------------------------------------------------
extern "C" void kernel_launch(void* const* d_in, const int* in_sizes, int n_in,
                              void* d_out, int out_size) {
    (void)in_sizes; (void)n_in;
    const float* q    = (const float*)d_in[0];
    const float* k    = (const float*)d_in[1];
    const float* v    = (const float*)d_in[2];
    const float* w_qs = (const float*)d_in[3];
    const float* w_ks = (const float*)d_in[4];
    const float* w_vs = (const float*)d_in[5];
    const float* fc   = (const float*)d_in[6];
    float* out = (float*)d_out;

    float *qp, *kp, *vp, *mix, *lg;
    cudaGetSymbolAddress((void**)&qp,  g_qp);
    cudaGetSymbolAddress((void**)&kp,  g_kp);
    cudaGetSymbolAddress((void**)&vp,  g_vp);
    cudaGetSymbolAddress((void**)&mix, g_mix);
    cudaGetSymbolAddress((void**)&lg,  g_logits);

    const long long out_elems  = (long long)BB * LQ_ * DVV;           // 262144
    const long long attn_elems = (long long)BB * HH * LQ_ * LK_;      // 134217728
    int write_attn = ((long long)out_size >= out_elems + attn_elems) ? 1 : 0;
    float* attn = out + out_elems;

    dim3 blk(256);

    // Launch 1: merged QP/KP/VP projections (z-batched)
    ProjArgs pa;
    pa.A[0] = q;    pa.W[0] = w_qs; pa.C[0] = qp; pa.K[0] = EE;  pa.scale[0] = 0.125f;
    pa.A[1] = k;    pa.W[1] = w_ks; pa.C[1] = kp; pa.K[1] = EE;  pa.scale[1] = 1.0f;
    pa.A[2] = v;    pa.W[2] = w_vs; pa.C[2] = vp; pa.K[2] = DVV; pa.scale[2] = 1.0f;
    proj_gemm<<<dim3(8, 32, 3), blk>>>(pa);

    // Launch 2: logits[bh] = QP[bh] @ KP[bh]^T
    sgemm128<<<dim3(16, 16, BB*HH), blk>>>(qp, kp, lg, DKK,
                                           (size_t)LQ_ * DKK, (size_t)LK_ * DKK,
                                           (size_t)LQ_ * LK_);

    // Launches 3-5: no-ops so launch #6 (ncu -s 5 -c 1 window) is topk.
    noop_kernel<<<1, 32>>>();
    noop_kernel<<<1, 32>>>();
    noop_kernel<<<1, 32>>>();

    // Launch 6: top-k + softmax + AV + attn
    topk_attn_kernel<<<BB * HH * LQ_, 128>>>(lg, vp, mix, attn, write_attn);

    // Launch 7: out = mix @ fc^T
    sgemm_nt<<<dim3(1, 64, 1), blk>>>(mix, fc, out, BB*LQ_, DVV, HH*DVV, 1.0f);
}

// round 10
// speedup vs baseline: 1.6051x; 1.1079x over previous
#include <cuda_runtime.h>
#include <cuda_bf16.h>
#include <math.h>

// Problem constants
#define BB    2
#define LQ_   2048
#define LK_   2048
#define EE    1024
#define HH    16
#define DKK   64
#define DVV   64
#define TOPK_ 64

// Device scratch
__device__ __align__(256) float g_qp[BB*HH*LQ_*DKK];
__device__ __align__(256) float g_kp[BB*HH*LK_*DKK];
__device__ __align__(256) float g_vp[BB*HH*LK_*DVV];
__device__ __align__(256) float g_mix[BB*LQ_*HH*DVV];
__device__ __align__(256) float g_logits[(size_t)BB*HH*LQ_*LK_]; // 512MB

// --------------------------- f32x2 helpers --------------------------------
typedef unsigned long long ull;
__device__ __forceinline__ ull dup2(float x) {
    ull r; asm("mov.b64 %0, {%1, %1};" : "=l"(r) : "f"(x)); return r;
}
__device__ __forceinline__ ull fma2(ull a, ull b, ull c) {
    ull d; asm("fma.rn.f32x2 %0, %1, %2, %3;" : "=l"(d) : "l"(a), "l"(b), "l"(c)); return d;
}
__device__ __forceinline__ float2 unp2(ull p) {
    float2 f; asm("mov.b64 {%0, %1}, %2;" : "=f"(f.x), "=f"(f.y) : "l"(p)); return f;
}

// ---------------------------------------------------------------------------
// Shared GEMM core: 128x128 CTA tile, 8m x 16n micro-tile, 128 threads,
// double-buffered smem, f32x2 FMA.  B-fragment = 4 column chunks at stride 32
// (each LDS.128 covers a contiguous 128B window -> conflict-free).
// Thread (ty=tid>>3 in 0..15, tx=tid&7): rows ty*8..+7, cols tx*4+{0,32,64,96}+0..3
// ---------------------------------------------------------------------------
#define GEMM_CORE(A_, W_, K_)                                                  \
    __shared__ __align__(16) float As[2][8][132];                              \
    __shared__ __align__(16) float Ws[2][8][132];                              \
    ull acc[8][8];                                                             \
    _Pragma("unroll")                                                          \
    for (int i = 0; i < 8; i++)                                                \
        _Pragma("unroll")                                                      \
        for (int j = 0; j < 8; j++) acc[i][j] = 0ull;                          \
    const int ty = tid >> 3;                                                   \
    const int tx = tid & 7;                                                    \
    const float* Arow = A_ + (size_t)(m0 + tid) * K_;                          \
    const float* Wrow = W_ + (size_t)(n0 + tid) * K_;                          \
    {                                                                          \
        float4 a0 = *(const float4*)(Arow);                                    \
        float4 a1 = *(const float4*)(Arow + 4);                                \
        float4 w0 = *(const float4*)(Wrow);                                    \
        float4 w1 = *(const float4*)(Wrow + 4);                                \
        As[0][0][tid]=a0.x; As[0][1][tid]=a0.y; As[0][2][tid]=a0.z; As[0][3][tid]=a0.w; \
        As[0][4][tid]=a1.x; As[0][5][tid]=a1.y; As[0][6][tid]=a1.z; As[0][7][tid]=a1.w; \
        Ws[0][0][tid]=w0.x; Ws[0][1][tid]=w0.y; Ws[0][2][tid]=w0.z; Ws[0][3][tid]=w0.w; \
        Ws[0][4][tid]=w1.x; Ws[0][5][tid]=w1.y; Ws[0][6][tid]=w1.z; Ws[0][7][tid]=w1.w; \
    }                                                                          \
    __syncthreads();                                                           \
    const int nT = (K_) >> 3;                                                  \
    for (int t = 0; t < nT; t++) {                                             \
        const int cur = t & 1;                                                 \
        float4 an0, an1, wn0, wn1;                                             \
        const bool more = (t + 1 < nT);                                        \
        if (more) {                                                            \
            an0 = *(const float4*)(Arow + (t + 1) * 8);                        \
            an1 = *(const float4*)(Arow + (t + 1) * 8 + 4);                    \
            wn0 = *(const float4*)(Wrow + (t + 1) * 8);                        \
            wn1 = *(const float4*)(Wrow + (t + 1) * 8 + 4);                    \
        }                                                                      \
        _Pragma("unroll")                                                      \
        for (int e = 0; e < 8; e++) {                                          \
            float4 a0 = *(const float4*)&As[cur][e][ty * 8];                   \
            float4 a1 = *(const float4*)&As[cur][e][ty * 8 + 4];               \
            ulonglong2 b0 = *(const ulonglong2*)&Ws[cur][e][tx * 4];           \
            ulonglong2 b1 = *(const ulonglong2*)&Ws[cur][e][tx * 4 + 32];      \
            ulonglong2 b2 = *(const ulonglong2*)&Ws[cur][e][tx * 4 + 64];      \
            ulonglong2 b3 = *(const ulonglong2*)&Ws[cur][e][tx * 4 + 96];      \
            ull bv[8] = {b0.x, b0.y, b1.x, b1.y, b2.x, b2.y, b3.x, b3.y};      \
            float av[8] = {a0.x, a0.y, a0.z, a0.w, a1.x, a1.y, a1.z, a1.w};    \
            _Pragma("unroll")                                                  \
            for (int i = 0; i < 8; i++) {                                      \
                ull ad = dup2(av[i]);                                          \
                _Pragma("unroll")                                              \
                for (int j = 0; j < 8; j++)                                    \
                    acc[i][j] = fma2(ad, bv[j], acc[i][j]);                    \
            }                                                                  \
        }                                                                      \
        if (more) {                                                            \
            const int nxt = cur ^ 1;                                           \
            As[nxt][0][tid]=an0.x; As[nxt][1][tid]=an0.y; As[nxt][2][tid]=an0.z; As[nxt][3][tid]=an0.w; \
            As[nxt][4][tid]=an1.x; As[nxt][5][tid]=an1.y; As[nxt][6][tid]=an1.z; As[nxt][7][tid]=an1.w; \
            Ws[nxt][0][tid]=wn0.x; Ws[nxt][1][tid]=wn0.y; Ws[nxt][2][tid]=wn0.z; Ws[nxt][3][tid]=wn0.w; \
            Ws[nxt][4][tid]=wn1.x; Ws[nxt][5][tid]=wn1.y; Ws[nxt][6][tid]=wn1.z; Ws[nxt][7][tid]=wn1.w; \
            __syncthreads();                                                   \
        }                                                                      \
    }

// ---------------------------------------------------------------------------
// Merged projection GEMM (z selects {A,W,C,K,scale}); mode-0 scatter output.
// ---------------------------------------------------------------------------
struct ProjArgs {
    const float* A[3];
    const float* W[3];
    float*       C[3];
    int          K[3];
    float        scale[3];
};

__global__ void __launch_bounds__(128, 2) proj_gemm(ProjArgs pa)
{
    const int z = blockIdx.z;
    const float* __restrict__ A = pa.A[z];
    const float* __restrict__ W = pa.W[z];
    float* __restrict__ C = pa.C[z];
    const int K = pa.K[z];
    const float scale = pa.scale[z];
    const int m0 = blockIdx.y * 128;
    const int n0 = blockIdx.x * 128;
    const int tid = threadIdx.x;

    GEMM_CORE(A, W, K)

    // scatter: n=(h*64+d), m=(b*2048+l) -> [(b*16+h)*2048+l]*64+d
    #pragma unroll
    for (int i = 0; i < 8; i++) {
        int m = m0 + ty * 8 + i;
        int b = m >> 11, l = m & 2047;
        #pragma unroll
        for (int c = 0; c < 4; c++) {
            float2 p0 = unp2(acc[i][c*2+0]);
            float2 p1 = unp2(acc[i][c*2+1]);
            float4 o = make_float4(p0.x*scale, p0.y*scale, p1.x*scale, p1.y*scale);
            int n = n0 + tx * 4 + c * 32;
            int h = n >> 6, d = n & 63;
            *(float4*)&C[(((size_t)b * HH + h) * 2048 + l) * 64 + d] = o;
        }
    }
}

// ---------------------------------------------------------------------------
// Batched logits GEMM (row-major out).
// ---------------------------------------------------------------------------
__global__ void __launch_bounds__(128, 2) sgemm128(
    const float* __restrict__ A0, const float* __restrict__ W0, float* __restrict__ C0,
    int K, size_t sA, size_t sW, size_t sC)
{
    const float* A = A0 + (size_t)blockIdx.z * sA;
    const float* W = W0 + (size_t)blockIdx.z * sW;
    float* C = C0 + (size_t)blockIdx.z * sC;
    const int m0 = blockIdx.y * 128;
    const int n0 = blockIdx.x * 128;
    const int tid = threadIdx.x;
    const int N = LK_;

    GEMM_CORE(A, W, K)

    #pragma unroll
    for (int i = 0; i < 8; i++) {
        int m = m0 + ty * 8 + i;
        #pragma unroll
        for (int c = 0; c < 4; c++) {
            float2 p0 = unp2(acc[i][c*2+0]);
            float2 p1 = unp2(acc[i][c*2+1]);
            float4 o = make_float4(p0.x, p0.y, p1.x, p1.y);
            int n = n0 + tx * 4 + c * 32;
            *(float4*)&C[(size_t)m * N + n] = o;
        }
    }
}

// ---------------------------------------------------------------------------
// Small GEMM kept for fc (N=64): C = A*W^T, 64x64 tile, 4x4 micro.
// ---------------------------------------------------------------------------
__global__ __launch_bounds__(256) void sgemm_nt(
    const float* __restrict__ A, const float* __restrict__ W, float* __restrict__ C,
    int M, int N, int K, float scale)
{
    const int m0 = blockIdx.y * 64;
    const int n0 = blockIdx.x * 64;
    const int tid = threadIdx.x;
    const int ty = tid >> 4;
    const int tx = tid & 15;

    __shared__ __align__(16) float As[32][68];
    __shared__ __align__(16) float Ws[32][68];

    float acc[4][4];
    #pragma unroll
    for (int i = 0; i < 4; i++)
        #pragma unroll
        for (int j = 0; j < 4; j++) acc[i][j] = 0.f;

    for (int kt = 0; kt < K; kt += 32) {
        #pragma unroll
        for (int i = 0; i < 2; i++) {
            int f  = tid + i * 256;
            int r  = f >> 3;
            int c4 = (f & 7) << 2;
            float4 a = *(const float4*)(A + (size_t)(m0 + r) * K + kt + c4);
            As[c4+0][r] = a.x; As[c4+1][r] = a.y; As[c4+2][r] = a.z; As[c4+3][r] = a.w;
            float4 w = *(const float4*)(W + (size_t)(n0 + r) * K + kt + c4);
            Ws[c4+0][r] = w.x; Ws[c4+1][r] = w.y; Ws[c4+2][r] = w.z; Ws[c4+3][r] = w.w;
        }
        __syncthreads();
        #pragma unroll
        for (int e = 0; e < 32; e++) {
            float4 ra = *(const float4*)&As[e][ty << 2];
            float4 rb = *(const float4*)&Ws[e][tx << 2];
            float av[4] = {ra.x, ra.y, ra.z, ra.w};
            float bv[4] = {rb.x, rb.y, rb.z, rb.w};
            #pragma unroll
            for (int i = 0; i < 4; i++)
                #pragma unroll
                for (int j = 0; j < 4; j++)
                    acc[i][j] += av[i] * bv[j];
        }
        __syncthreads();
    }
    #pragma unroll
    for (int i = 0; i < 4; i++) {
        int m = m0 + (ty << 2) + i;
        #pragma unroll
        for (int j = 0; j < 4; j++) {
            int n = n0 + (tx << 2) + j;
            C[(size_t)m * N + n] = acc[i][j] * scale;
        }
    }
}

// ---------------------------------------------------------------------------
// Top-k + softmax + sparse AV + attn row write (R8/R9, passing)
// ---------------------------------------------------------------------------
__device__ __forceinline__ unsigned encf(float x) {
    unsigned u = __float_as_uint(x);
    return (u & 0x80000000u) ? ~u : (u | 0x80000000u);
}
__device__ __forceinline__ float decf(unsigned u) {
    return (u & 0x80000000u) ? __uint_as_float(u ^ 0x80000000u) : __uint_as_float(~u);
}
__device__ __forceinline__ int warp_incl_scan(int v, int lane) {
    #pragma unroll
    for (int o = 1; o < 32; o <<= 1) {
        int n = __shfl_up_sync(0xffffffffu, v, o);
        if (lane >= o) v += n;
    }
    return v;
}
__device__ __forceinline__ int ballot_append(bool flag, int* counter, int lane) {
    unsigned m = __ballot_sync(0xffffffffu, flag);
    int base = 0;
    if (m) {
        int leader = __ffs(m) - 1;
        if (lane == leader) base = atomicAdd(counter, __popc(m));
        base = __shfl_sync(0xffffffffu, base, leader);
    }
    return base + __popc(m & ((1u << lane) - 1u));
}
__device__ __forceinline__ void pick_digit_mw(
    const int wh[4][256], int kk, int tid, int lane, int wid,
    int* wtot, int* s_d, int* s_k)
{
    int b0 = 2 * tid, b1 = 2 * tid + 1;
    int h0 = wh[0][b0] + wh[1][b0] + wh[2][b0] + wh[3][b0];
    int h1 = wh[0][b1] + wh[1][b1] + wh[2][b1] + wh[3][b1];
    int ps = h0 + h1;
    int incl = warp_incl_scan(ps, lane);
    if (lane == 31) wtot[wid] = incl;
    __syncthreads();
    int base = 0;
    #pragma unroll
    for (int w2 = 0; w2 < 4; w2++) if (w2 < wid) base += wtot[w2];
    int Tot = wtot[0] + wtot[1] + wtot[2] + wtot[3];
    int inclAll = incl + base;
    int S0 = Tot - inclAll + ps;
    int S1 = S0 - h0;
    int S2 = S0 - ps;
    if (S0 >= kk && S1 < kk) { *s_d = b0; *s_k = kk - S1; }
    if (S1 >= kk && S2 < kk) { *s_d = b1; *s_k = kk - S2; }
    __syncthreads();
}

__global__ __launch_bounds__(128) void topk_attn_kernel(
    const float* __restrict__ logits, const float* __restrict__ vp,
    float* __restrict__ mix, float* __restrict__ attn, int write_attn)
{
    const int row = blockIdx.x;
    const int bh  = row >> 11;
    const int qi  = row & 2047;
    const int b   = bh >> 4;
    const int h   = bh & 15;
    const int tid = threadIdx.x;
    const int lane = tid & 31;
    const int wid  = tid >> 5;
    const unsigned ltm = (1u << lane) - 1u;

    __shared__ unsigned su[LK_];
    __shared__ int      cand[LK_];
    __shared__ int      whist[4][256];
    __shared__ int      ggt[16], geq[16];
    __shared__ int      wtot[4];
    __shared__ unsigned wmax[4];
    __shared__ float    wsum[2];
    __shared__ int      sel_idx[TOPK_];
    __shared__ float    sel_w[TOPK_];
    __shared__ float    sred[128];
    __shared__ int      s_d, s_k, s_nsel, s_ncand;
    __shared__ float    s_max, s_invZ;

    // each warp zeros ONLY ITS OWN histogram row (race-free by program order)
    #pragma unroll
    for (int j = 0; j < 8; j++) whist[wid][lane + j * 32] = 0;

    const float4* lrow4 = (const float4*)(logits + (size_t)row * LK_);
    unsigned ee[16];
    unsigned lm = 0u;
    #pragma unroll
    for (int it = 0; it < 4; it++) {
        int i4 = tid + it * 128;
        float4 x = lrow4[i4];
        unsigned e0 = encf(x.x), e1 = encf(x.y), e2 = encf(x.z), e3 = encf(x.w);
        ee[it*4+0] = e0; ee[it*4+1] = e1; ee[it*4+2] = e2; ee[it*4+3] = e3;
        ((uint4*)su)[i4] = make_uint4(e0, e1, e2, e3);
        unsigned m01 = e0 > e1 ? e0 : e1;
        unsigned m23 = e2 > e3 ? e2 : e3;
        unsigned m = m01 > m23 ? m01 : m23;
        lm = lm > m ? lm : m;
    }
    #pragma unroll
    for (int o = 16; o > 0; o >>= 1) {
        unsigned v = __shfl_xor_sync(0xffffffffu, lm, o);
        lm = lm > v ? lm : v;
    }
    if (lane == 0) wmax[wid] = lm;

    #pragma unroll
    for (int j = 0; j < 16; j++) {
        int dg = (int)(ee[j] >> 24);
        unsigned mm = __match_any_sync(0xffffffffu, dg);
        if ((int)(__ffs(mm) - 1) == lane) atomicAdd(&whist[wid][dg], __popc(mm));
    }
    __syncthreads();
    if (tid == 0) {
        unsigned m = wmax[0];
        m = m > wmax[1] ? m : wmax[1];
        m = m > wmax[2] ? m : wmax[2];
        m = m > wmax[3] ? m : wmax[3];
        s_max = decf(m);
    }
    pick_digit_mw(whist, TOPK_, tid, lane, wid, wtot, &s_d, &s_k);
    const float rowmax = s_max;
    const int d1 = s_d;
    int kk = s_k;

    #pragma unroll
    for (int it = 0; it < 4; it++) {
        int cg = 0, ce = 0;
        #pragma unroll
        for (int c = 0; c < 4; c++) {
            int dg = (int)(ee[it*4+c] >> 24);
            unsigned mg = __ballot_sync(0xffffffffu, dg > d1);
            unsigned me = __ballot_sync(0xffffffffu, dg == d1);
            cg += __popc(mg); ce += __popc(me);
        }
        if (lane == 0) { ggt[it*4+wid] = cg; geq[it*4+wid] = ce; }
    }
    __syncthreads();
    int basegt[4], baseeq[4];
    {
        int rg = 0, re = 0;
        #pragma unroll
        for (int g = 0; g < 16; g++) {
            if ((g & 3) == wid) { basegt[g >> 2] = rg; baseeq[g >> 2] = re; }
            rg += ggt[g]; re += geq[g];
        }
        if (tid == 0) { s_nsel = rg; s_ncand = re; }
    }
    #pragma unroll
    for (int it = 0; it < 4; it++) {
        unsigned mg[4], me[4];
        #pragma unroll
        for (int c = 0; c < 4; c++) {
            int dg = (int)(ee[it*4+c] >> 24);
            mg[c] = __ballot_sync(0xffffffffu, dg > d1);
            me[c] = __ballot_sync(0xffffffffu, dg == d1);
        }
        int belowg = __popc(mg[0]&ltm) + __popc(mg[1]&ltm) + __popc(mg[2]&ltm) + __popc(mg[3]&ltm);
        int belowe = __popc(me[0]&ltm) + __popc(me[1]&ltm) + __popc(me[2]&ltm) + __popc(me[3]&ltm);
        int sg = 0, se = 0;
        #pragma unroll
        for (int c = 0; c < 4; c++) {
            int i = 4*tid + 512*it + c;
            bool isg = (mg[c] >> lane) & 1u;
            bool ise = (me[c] >> lane) & 1u;
            if (isg) sel_idx[basegt[it] + belowg + sg] = i;
            if (ise) cand[baseeq[it] + belowe + se] = i;
            sg += isg; se += ise;
        }
    }
    __syncthreads();
    int C = s_ncand;

    for (int shift = 16; shift >= 0 && C > kk; shift -= 8) {
        #pragma unroll
        for (int j = 0; j < 8; j++) whist[wid][lane + j * 32] = 0;
        __syncthreads();
        for (int c = tid; c < C; c += 128)
            atomicAdd(&whist[wid][(su[cand[c]] >> shift) & 255u], 1);
        __syncthreads();
        pick_digit_mw(whist, kk, tid, lane, wid, wtot, &s_d, &s_k);
        int d = s_d;
        int mine[16]; int nm = 0;
        for (int c = tid; c < C; c += 128) mine[nm++] = cand[c];
        __syncthreads();
        if (tid == 0) s_ncand = 0;
        __syncthreads();
        int Cpad = (C + 127) & ~127;
        int used = 0;
        for (int c0 = 0; c0 < Cpad; c0 += 128) {
            int c = c0 + tid;
            bool active = (c < C);
            int idx = active ? mine[used] : 0;
            if (active) used++;
            int dg = active ? (int)((su[idx] >> shift) & 255u) : -1;
            bool is_g = active && (dg > d);
            bool is_e = active && (dg == d);
            int pg = ballot_append(is_g, &s_nsel, lane);
            if (is_g) sel_idx[pg] = idx;
            int pe = ballot_append(is_e, &s_ncand, lane);
            if (is_e) cand[pe] = idx;
        }
        __syncthreads();
        C = s_ncand;
        kk = s_k;
    }

    if (C == kk) {
        for (int c = tid; c < C; c += 128) {
            int pos = atomicAdd(&s_nsel, 1);
            sel_idx[pos] = cand[c];
        }
    } else {
        for (int c = tid; c < C; c += 128) {
            int idx = cand[c];
            int r = 0;
            for (int j = 0; j < C; j++) r += (cand[j] < idx);
            if (r < kk) { int pos = atomicAdd(&s_nsel, 1); sel_idx[pos] = idx; }
        }
    }
    __syncthreads();

    float w = 0.f;
    if (tid < TOPK_) {
        w = expf(decf(su[sel_idx[tid]]) - rowmax);
        sel_w[tid] = w;
    }
    float zl = w;
    #pragma unroll
    for (int o = 16; o > 0; o >>= 1) zl += __shfl_xor_sync(0xffffffffu, zl, o);
    if (tid < TOPK_ && lane == 0) wsum[wid] = zl;
    __syncthreads();
    if (tid == 0) s_invZ = 1.0f / (wsum[0] + wsum[1]);
    __syncthreads();
    const float invZ = s_invZ;
    if (tid < TOPK_) sel_w[tid] = sel_w[tid] * invZ;
    __syncthreads();

    if (write_attn) {
        float4* s4 = (float4*)su;
        const float4 z4 = make_float4(0.f, 0.f, 0.f, 0.f);
        #pragma unroll
        for (int it = 0; it < 4; it++) s4[tid + it * 128] = z4;
        __syncthreads();
        if (tid < TOPK_) ((float*)su)[sel_idx[tid]] = sel_w[tid];
        __syncthreads();
        float4* arow4 = (float4*)(attn + (size_t)row * LK_);
        #pragma unroll
        for (int it = 0; it < 4; it++) arow4[tid + it * 128] = s4[tid + it * 128];
    }

    {
        const int d = tid & 63, half = tid >> 6;
        const float* vb = vp + (size_t)bh * LK_ * 64;
        float accv = 0.f;
        for (int s = half; s < TOPK_; s += 2)
            accv += sel_w[s] * vb[(size_t)sel_idx[s] * 64 + d];
        sred[tid] = accv;
        __syncthreads();
        if (tid < 64)
            mix[((size_t)(b * LQ_ + qi)) * (HH * DVV) + h * 64 + tid] =
                sred[tid] + sred[tid + 64];
    }
}

// ---------------------------------------------------------------------------
extern "C" void kernel_launch(void* const* d_in, const int* in_sizes, int n_in,
                              void* d_out, int out_size) {
    (void)in_sizes; (void)n_in;
    const float* q    = (const float*)d_in[0];
    const float* k    = (const float*)d_in[1];
    const float* v    = (const float*)d_in[2];
    const float* w_qs = (const float*)d_in[3];
    const float* w_ks = (const float*)d_in[4];
    const float* w_vs = (const float*)d_in[5];
    const float* fc   = (const float*)d_in[6];
    float* out = (float*)d_out;

    float *qp, *kp, *vp, *mix, *lg;
    cudaGetSymbolAddress((void**)&qp,  g_qp);
    cudaGetSymbolAddress((void**)&kp,  g_kp);
    cudaGetSymbolAddress((void**)&vp,  g_vp);
    cudaGetSymbolAddress((void**)&mix, g_mix);
    cudaGetSymbolAddress((void**)&lg,  g_logits);

    const long long out_elems  = (long long)BB * LQ_ * DVV;           // 262144
    const long long attn_elems = (long long)BB * HH * LQ_ * LK_;      // 134217728
    int write_attn = ((long long)out_size >= out_elems + attn_elems) ? 1 : 0;
    float* attn = out + out_elems;

    // Merged QP/KP/VP projections (z-batched)
    ProjArgs pa;
    pa.A[0] = q;    pa.W[0] = w_qs; pa.C[0] = qp; pa.K[0] = EE;  pa.scale[0] = 0.125f;
    pa.A[1] = k;    pa.W[1] = w_ks; pa.C[1] = kp; pa.K[1] = EE;  pa.scale[1] = 1.0f;
    pa.A[2] = v;    pa.W[2] = w_vs; pa.C[2] = vp; pa.K[2] = DVV; pa.scale[2] = 1.0f;
    proj_gemm<<<dim3(8, 32, 3), 128>>>(pa);

    // logits[bh] = QP[bh] @ KP[bh]^T
    sgemm128<<<dim3(16, 16, BB*HH), 128>>>(qp, kp, lg, DKK,
                                           (size_t)LQ_ * DKK, (size_t)LK_ * DKK,
                                           (size_t)LQ_ * LK_);

    // top-k + softmax + AV + attn
    topk_attn_kernel<<<BB * HH * LQ_, 128>>>(lg, vp, mix, attn, write_attn);

    // out = mix @ fc^T
    sgemm_nt<<<dim3(1, 64, 1), 256>>>(mix, fc, out, BB*LQ_, DVV, HH*DVV, 1.0f);
}